// round 13
// baseline (speedup 1.0000x reference)
#include <cuda_runtime.h>
#include <math.h>

#define BB 64
#define TT 256
#define EE 300
#define HH 256
#define G4H 1024
#define NINTER 128
#define NL 17
#define TL 19
#define START_IDX 17
#define END_IDX 18
#define LOW_POT -10000.0f

typedef unsigned long long ull;

// ---------------- device scratch (static; no allocations allowed) ----------------
__device__ float g_xp[2][TT][G4H][BB];        // x_proj, [dir][t][gate_row][b]
__device__ float g_h[2][2][HH][BB];           // h state double-buffered, [k][b]
__device__ float g_hs[TT][2 * HH][BB];        // hidden history, [t][k][b]
__device__ float g_unary[BB][TT][NL];         // classifier outputs
__device__ unsigned int g_bar_count;
__device__ volatile unsigned int g_bar_gen;
__device__ volatile unsigned int g_flag2[2][64][8];   // per-dir flags, 32B-padded

// ---------------- atomic grid barrier (flag reset at end of lstm) ---------------
__device__ __forceinline__ void grid_barrier(unsigned nb)
{
    __syncthreads();
    if (threadIdx.x == 0) {
        unsigned g = g_bar_gen;
        __threadfence();
        unsigned t = atomicAdd(&g_bar_count, 1u);
        if (t == nb - 1u) {
            g_bar_count = 0u;
            __threadfence();
            g_bar_gen = g + 1u;
        } else {
            while (g_bar_gen == g) { }
        }
        __threadfence();
    }
    __syncthreads();
}

// ---------------- cp.async helpers ----------------
__device__ __forceinline__ void cp_async16(unsigned smem_addr, const void* gptr)
{
    asm volatile("cp.async.cg.shared.global [%0], [%1], 16;\n"
                 :: "r"(smem_addr), "l"(gptr));
}
__device__ __forceinline__ void cp_commit()
{
    asm volatile("cp.async.commit_group;\n");
}
template <int N>
__device__ __forceinline__ void cp_wait()
{
    asm volatile("cp.async.wait_group %0;\n" :: "n"(N));
}

// ---------------- acquire load for flag polling ----------------
__device__ __forceinline__ unsigned ld_acquire_gpu(volatile unsigned* p)
{
    unsigned v;
    asm volatile("ld.acquire.gpu.global.u32 %0, [%1];"
                 : "=r"(v) : "l"((const unsigned*)p) : "memory");
    return v;
}

// ---------------- tf32 helpers (xproj) ----------------
__device__ __forceinline__ unsigned f2tf32(float f)
{
    unsigned u;
    asm("cvt.rna.tf32.f32 %0, %1;" : "=r"(u) : "f"(f));
    return u;
}
__device__ __forceinline__ void mma_tf32(float c[4], const unsigned a[4], const unsigned b[2])
{
    asm volatile("mma.sync.aligned.m16n8k8.row.col.f32.tf32.tf32.f32 "
                 "{%0,%1,%2,%3}, {%4,%5,%6,%7}, {%8,%9}, {%0,%1,%2,%3};"
                 : "+f"(c[0]), "+f"(c[1]), "+f"(c[2]), "+f"(c[3])
                 : "r"(a[0]), "r"(a[1]), "r"(a[2]), "r"(a[3]),
                   "r"(b[0]), "r"(b[1]));
}

// ---------------- packed f32x2 helpers ----------------
__device__ __forceinline__ void fma2(ull& d, ull a, ull b)
{
    asm("fma.rn.f32x2 %0, %1, %2, %0;" : "+l"(d) : "l"(a), "l"(b));
}
__device__ __forceinline__ ull splat2(float x)
{
    ull r;
    asm("mov.b64 %0, {%1, %1};" : "=l"(r) : "r"(__float_as_uint(x)));
    return r;
}
__device__ __forceinline__ ull pack2(float lo, float hi)
{
    ull r;
    asm("mov.b64 %0, {%1, %2};" : "=l"(r) : "r"(__float_as_uint(lo)), "r"(__float_as_uint(hi)));
    return r;
}
__device__ __forceinline__ float2 unpack2(ull v)
{
    unsigned lo, hi;
    asm("mov.b64 {%0, %1}, %2;" : "=r"(lo), "=r"(hi) : "l"(v));
    return make_float2(__uint_as_float(lo), __uint_as_float(hi));
}

// =======================================================================
// Kernel A: embedding gather + x_proj GEMM via 3xTF32 tensor cores.
// 4 token-tiles per block; W chunk conversion amortized. (R8 exact)
// =======================================================================
__global__ void __launch_bounds__(256, 1)
xproj_kernel(const int* __restrict__ x,
             const float* __restrict__ emb,
             const float* __restrict__ Wf,
             const float* __restrict__ bf,
             const float* __restrict__ Wb,
             const float* __restrict__ bb)
{
    __shared__ unsigned sWh[16][72], sWl[16][72];       // W chunk [k][m]
    __shared__ unsigned sEh[4][16][72], sEl[4][16][72]; // E chunks [t][k][n]
    __shared__ int sTok[4][64];

    int tg0 = blockIdx.x * 4;       // 4 consecutive t
    int gt = blockIdx.y;            // 0..31
    int dir = gt >> 4;
    int grow0 = (gt & 15) * 64;
    const float* W = dir ? Wb : Wf;
    const float* bias = dir ? bb : bf;

    int tid = threadIdx.x;
    int warp = tid >> 5, lane = tid & 31;
    int m0 = (warp & 3) * 16;
    int n0 = (warp >> 2) * 32;

    {
        int tt = tid >> 6, b = tid & 63;
        sTok[tt][b] = x[b * TT + (tg0 + tt)];
    }
    __syncthreads();

    float acc[4][4][4];             // [t][n-subtile][C regs]
#pragma unroll
    for (int tt = 0; tt < 4; tt++)
#pragma unroll
        for (int j = 0; j < 4; j++)
#pragma unroll
            for (int c = 0; c < 4; c++) acc[tt][j][c] = 0.f;

    float rw[4], re[16];

#define LOAD_CHUNK(kc)                                                        \
    {                                                                         \
        _Pragma("unroll")                                                     \
        for (int i = 0; i < 4; i++) {                                         \
            int idx = i * 256 + tid;                                          \
            int mm = idx >> 4, kk = (kc) + (idx & 15);                        \
            rw[i] = (kk < EE) ? W[(grow0 + mm) * EE + kk] : 0.f;              \
        }                                                                     \
        _Pragma("unroll")                                                     \
        for (int i = 0; i < 16; i++) {                                        \
            int idx = i * 256 + tid;                                          \
            int tt = idx >> 10, rem = idx & 1023;                             \
            int mm = rem >> 4, kk = (kc) + (rem & 15);                        \
            re[i] = (kk < EE) ? emb[(long)sTok[tt][mm] * EE + kk] : 0.f;      \
        }                                                                     \
    }

    LOAD_CHUNK(0)

    for (int c = 0; c < 19; c++) {
        __syncthreads();
#pragma unroll
        for (int i = 0; i < 4; i++) {
            int idx = i * 256 + tid;
            int mm = idx >> 4, k = idx & 15;
            float fw = rw[i];
            unsigned wh = f2tf32(fw);
            sWh[k][mm] = wh;
            sWl[k][mm] = f2tf32(fw - __uint_as_float(wh));
        }
#pragma unroll
        for (int i = 0; i < 16; i++) {
            int idx = i * 256 + tid;
            int tt = idx >> 10, rem = idx & 1023;
            int mm = rem >> 4, k = rem & 15;
            float fe = re[i];
            unsigned eh = f2tf32(fe);
            sEh[tt][k][mm] = eh;
            sEl[tt][k][mm] = f2tf32(fe - __uint_as_float(eh));
        }
        __syncthreads();
        if (c + 1 < 19) LOAD_CHUNK((c + 1) * 16)

#pragma unroll
        for (int kt = 0; kt < 2; kt++) {
            int ka = kt * 8 + (lane & 3);
            int ra = m0 + (lane >> 2);
            unsigned ah[4], al[4];
            ah[0] = sWh[ka][ra];     al[0] = sWl[ka][ra];
            ah[1] = sWh[ka][ra + 8]; al[1] = sWl[ka][ra + 8];
            ah[2] = sWh[ka + 4][ra];     al[2] = sWl[ka + 4][ra];
            ah[3] = sWh[ka + 4][ra + 8]; al[3] = sWl[ka + 4][ra + 8];
#pragma unroll
            for (int tt = 0; tt < 4; tt++) {
#pragma unroll
                for (int j = 0; j < 4; j++) {
                    int nb = n0 + j * 8 + (lane >> 2);
                    unsigned bh[2], bl[2];
                    bh[0] = sEh[tt][ka][nb];     bl[0] = sEl[tt][ka][nb];
                    bh[1] = sEh[tt][ka + 4][nb]; bl[1] = sEl[tt][ka + 4][nb];
                    mma_tf32(acc[tt][j], ah, bh);
                    mma_tf32(acc[tt][j], ah, bl);
                    mma_tf32(acc[tt][j], al, bh);
                }
            }
        }
    }
#undef LOAD_CHUNK

    int row = m0 + (lane >> 2);
    int colb = (lane & 3) * 2;
    float bv0 = bias[grow0 + row];
    float bv8 = bias[grow0 + row + 8];
#pragma unroll
    for (int tt = 0; tt < 4; tt++) {
        int t = tg0 + tt;
#pragma unroll
        for (int j = 0; j < 4; j++) {
            int col = n0 + j * 8 + colb;
            *(float2*)&g_xp[dir][t][grow0 + row][col] =
                make_float2(acc[tt][j][0] + bv0, acc[tt][j][1] + bv0);
            *(float2*)&g_xp[dir][t][grow0 + row + 8][col] =
                make_float2(acc[tt][j][2] + bv8, acc[tt][j][3] + bv8);
        }
    }
}

// =======================================================================
// Kernel B: persistent BiLSTM (R8 structure + split wait). 128 blocks.
// Poll producers 0..31, issue first-half copy, poll 32..63 while that
// copy is in flight, issue second half. Same 4 commit groups + GEMM
// interleave as R8. f32x2 GEMM (bit-identical to fp32).
// =======================================================================
__global__ void __launch_bounds__(256, 1)
lstm_kernel(const float* __restrict__ Whf,
            const float* __restrict__ Whb)
{
    extern __shared__ float sm[];
    ull*   sW2 = (ull*)sm;                       // 16 x 258 ull pairs (33 KB)
    float* sH  = sm + 2 * 16 * 258;              // 256 x 64 (64 KB)
    float* sG  = sH + 256 * 64;                  // 16 x 68

    int tid = threadIdx.x;
    int bid = blockIdx.x;               // 0..127
    int dir = bid & 1;
    int grp = bid >> 1;                 // 0..63
    int c0 = grp * 4;
    const float* Whh = dir ? Whb : Whf;

    // load + pre-splat 16 W_hh rows (row stride 258 ull, bank-safe)
    for (int idx = tid; idx < 4096; idx += 256) {
        int r = idx >> 8, k = idx & 255;
        int gate = r >> 2, ci = r & 3;
        float w = Whh[(gate * 256 + c0 + ci) * 256 + k];
        sW2[r * 258 + k] = splat2(w);
    }
    // zero-init own slice of h buffer 0
    g_h[dir][0][c0 + (tid >> 6)][tid & 63] = 0.f;
    float c_state = 0.f;

    int r = tid & 15, q = tid >> 4;     // phase-1 mapping: row r of 16, batch quad q
    int wrow = (r >> 2) * 256 + c0 + (r & 3);
    int ci2 = tid >> 6, b2 = tid & 63;  // phase-2 mapping: (col ci2, batch b2)

    unsigned sH_addr = (unsigned)__cvta_generic_to_shared(sH);
    const ull* wr2 = sW2 + r * 258;
    const ulonglong2* hq = (const ulonglong2*)sH + q;

    __syncthreads();
    if (tid == 0) { __threadfence(); g_flag2[dir][grp][0] = 1u; }

    for (int s = 0; s < TT; s++) {
        int t = dir ? (TT - 1 - s) : s;

        // prefetch x_proj tile (independent of flags)
        float4 a = __ldg((const float4*)&g_xp[dir][t][wrow][0] + q);

        // wait half 1: producers 0..31 (own h rows k = 0..127)
        if (tid < 32) {
            unsigned tgt = (unsigned)(s + 1);
            while (ld_acquire_gpu(&g_flag2[dir][tid][0]) < tgt) { }
        }
        __syncthreads();

        const float4* hsrc = (const float4*)&g_h[dir][s & 1][0][0];
#pragma unroll
        for (int g = 0; g < 2; g++) {
#pragma unroll
            for (int i = g * 4; i < g * 4 + 4; i++)
                cp_async16(sH_addr + (unsigned)((i * 256 + tid) * 16), hsrc + i * 256 + tid);
            cp_commit();
        }

        // wait half 2 (producers 32..63) while first 32KB is in flight
        if (tid < 32) {
            unsigned tgt = (unsigned)(s + 1);
            while (ld_acquire_gpu(&g_flag2[dir][32 + tid][0]) < tgt) { }
        }
        __syncthreads();

#pragma unroll
        for (int g = 2; g < 4; g++) {
#pragma unroll
            for (int i = g * 4; i < g * 4 + 4; i++)
                cp_async16(sH_addr + (unsigned)((i * 256 + tid) * 16), hsrc + i * 256 + tid);
            cp_commit();
        }

        ull acc0 = pack2(a.x, a.y);
        ull acc1 = pack2(a.z, a.w);

        cp_wait<3>();
        __syncthreads();
#pragma unroll 8
        for (int k = 0; k < 64; k++) {
            ull ww = wr2[k];
            ulonglong2 h2 = hq[k * 16];
            fma2(acc0, ww, h2.x);
            fma2(acc1, ww, h2.y);
        }
        cp_wait<2>();
        __syncthreads();
#pragma unroll 8
        for (int k = 64; k < 128; k++) {
            ull ww = wr2[k];
            ulonglong2 h2 = hq[k * 16];
            fma2(acc0, ww, h2.x);
            fma2(acc1, ww, h2.y);
        }
        cp_wait<1>();
        __syncthreads();
#pragma unroll 8
        for (int k = 128; k < 192; k++) {
            ull ww = wr2[k];
            ulonglong2 h2 = hq[k * 16];
            fma2(acc0, ww, h2.x);
            fma2(acc1, ww, h2.y);
        }
        cp_wait<0>();
        __syncthreads();
#pragma unroll 8
        for (int k = 192; k < 256; k++) {
            ull ww = wr2[k];
            ulonglong2 h2 = hq[k * 16];
            fma2(acc0, ww, h2.x);
            fma2(acc1, ww, h2.y);
        }
        {
            float2 v0 = unpack2(acc0), v1 = unpack2(acc1);
            *(float4*)&sG[r * 68 + q * 4] = make_float4(v0.x, v0.y, v1.x, v1.y);
        }
        __syncthreads();

        // phase 2: gate nonlinearity + state update for (col c0+ci2, batch b2)
        float gi = sG[(0 + ci2) * 68 + b2];
        float gf = sG[(4 + ci2) * 68 + b2];
        float gg = sG[(8 + ci2) * 68 + b2];
        float go = sG[(12 + ci2) * 68 + b2];
        float i_s = 1.f / (1.f + __expf(-gi));
        float f_s = 1.f / (1.f + __expf(-gf));
        float o_s = 1.f / (1.f + __expf(-go));
        float c_new = f_s * c_state + i_s * tanhf(gg);
        c_state = c_new;
        float h_new = o_s * tanhf(c_new);

        g_h[dir][(s + 1) & 1][c0 + ci2][b2] = h_new;        // coalesced
        g_hs[t][dir * 256 + c0 + ci2][b2] = h_new;          // coalesced ([t][k][b])

        __syncthreads();
        if (tid == 0) { __threadfence(); g_flag2[dir][grp][0] = (unsigned)(s + 2); }
    }

    // all blocks past every poll, then reset flags for the next graph replay
    grid_barrier(128u);
    if (tid == 0) g_flag2[dir][grp][0] = 0u;
}

// =======================================================================
// Kernel C: fc1 + ReLU + classifier -> unary. 256 blocks (one t each),
// f32x2 packed math. (R8 exact)
// =======================================================================
__global__ void fc_kernel(const float* __restrict__ fc1W,
                          const float* __restrict__ fc1b,
                          const float* __restrict__ clsW,
                          const float* __restrict__ clsb)
{
    extern __shared__ float sm[];
    float* sA = sm;                  // 32 x 64
    float* sB = sm + 2048;           // 32 x 128
    float* sI = sm + 6144;           // 64 x 128

    int tid = threadIdx.x;
    int t = blockIdx.x;

    int tr = tid >> 4, tn = tid & 15;
    int r0 = tr * 4, n0 = tn * 8;

    ull acc[4][4];
#pragma unroll
    for (int i = 0; i < 4; i++)
#pragma unroll
        for (int j = 0; j < 4; j++) acc[i][j] = 0ull;

    for (int kc = 0; kc < 512; kc += 32) {
        __syncthreads();
        for (int idx = tid; idx < 512; idx += 256) {
            int k = idx >> 4, b4 = idx & 15;
            *(float4*)&sA[k * 64 + b4 * 4] =
                *(const float4*)&g_hs[t][kc + k][b4 * 4];
        }
        for (int idx = tid; idx < 1024; idx += 256) {
            int n = idx >> 3, kq = idx & 7;
            float4 v = *(const float4*)&fc1W[n * 512 + kc + kq * 4];
            sB[(kq * 4 + 0) * 128 + n] = v.x;
            sB[(kq * 4 + 1) * 128 + n] = v.y;
            sB[(kq * 4 + 2) * 128 + n] = v.z;
            sB[(kq * 4 + 3) * 128 + n] = v.w;
        }
        __syncthreads();
#pragma unroll
        for (int k = 0; k < 32; k++) {
            float4 a4 = *(const float4*)&sA[k * 64 + r0];
            ull aw[4] = {splat2(a4.x), splat2(a4.y), splat2(a4.z), splat2(a4.w)};
            ulonglong2 bA = *(const ulonglong2*)&sB[k * 128 + n0];
            ulonglong2 bC = *(const ulonglong2*)&sB[k * 128 + n0 + 4];
#pragma unroll
            for (int i = 0; i < 4; i++) {
                fma2(acc[i][0], aw[i], bA.x);
                fma2(acc[i][1], aw[i], bA.y);
                fma2(acc[i][2], aw[i], bC.x);
                fma2(acc[i][3], aw[i], bC.y);
            }
        }
    }

#pragma unroll
    for (int i = 0; i < 4; i++)
#pragma unroll
        for (int j = 0; j < 4; j++) {
            float2 v = unpack2(acc[i][j]);
            int n = n0 + j * 2;
            sI[(r0 + i) * 128 + n]     = fmaxf(v.x + fc1b[n], 0.f);
            sI[(r0 + i) * 128 + n + 1] = fmaxf(v.y + fc1b[n + 1], 0.f);
        }
    __syncthreads();

    float* sCW = sA;
    for (int idx = tid; idx < NL * 128; idx += 256) {
        int l = idx >> 7, k = idx & 127;
        sCW[l * 129 + k] = clsW[idx];
    }
    __syncthreads();

    for (int oi = tid; oi < 64 * NL; oi += 256) {
        int b = oi / NL, l = oi % NL;
        const float* ip = &sI[b * 128];
        const float* wp = &sCW[l * 129];
        float s = 0.f;
#pragma unroll 8
        for (int k = 0; k < 128; k++) s += ip[k] * wp[k];
        g_unary[b][t][l] = s + clsb[l];
    }
}

// =======================================================================
// Kernel D: Viterbi decode. 16 blocks x 128 threads, 1 warp per batch.
// Unary staged in smem per warp (one-time coalesced load) -> in-loop
// access is LDS, hidden by 1-step prefetch.
// =======================================================================
__global__ void viterbi_kernel(const float* __restrict__ trans,
                               float* __restrict__ out)
{
    extern __shared__ float vsm[];
    float* sU = vsm;                                   // [4][256*20] floats
    float* tpn_s = vsm + 4 * 5120;                     // [19][20]
    unsigned char* bps = (unsigned char*)(vsm + 4 * 5120 + 384);  // [4][256][20]

    int tid = threadIdx.x;
    int warp = tid >> 5, lane = tid & 31;
    int b = blockIdx.x * 4 + warp;
    float* sUw = sU + warp * 5120;
    unsigned char* mybp = bps + warp * (256 * 20);

    // stage this batch's unary into smem (coalesced 4352-float copy)
    {
        const float* gu = &g_unary[b][0][0];
        for (int i = lane; i < TT * NL; i += 32)
            sUw[(i / NL) * 20 + (i % NL)] = __ldg(&gu[i]);
    }
    for (int i = tid; i < TL * TL; i += 128) {
        int p = i / TL, n = i % TL;
        tpn_s[p * 20 + n] = trans[n * TL + p];
    }
    __syncthreads();

    float tp[TL];
#pragma unroll
    for (int p = 0; p < TL; p++)
        tp[p] = (lane < TL) ? tpn_s[p * 20 + lane] : LOW_POT;

    float score = (lane == START_IDX) ? 0.f : LOW_POT;
    float u = (lane < NL) ? sUw[lane] : LOW_POT;

    for (int t = 0; t < TT; t++) {
        float u_next = (t + 1 < TT && lane < NL) ? sUw[(t + 1) * 20 + lane] : LOW_POT;

        float v[TL];
#pragma unroll
        for (int p = 0; p < TL; p++)
            v[p] = __shfl_sync(0xffffffffu, score, p) + tp[p];

        float w0 = fmaxf(v[0], v[1]),   w1 = fmaxf(v[2], v[3]);
        float w2 = fmaxf(v[4], v[5]),   w3 = fmaxf(v[6], v[7]);
        float w4 = fmaxf(v[8], v[9]),   w5 = fmaxf(v[10], v[11]);
        float w6 = fmaxf(v[12], v[13]), w7 = fmaxf(v[14], v[15]);
        float w8 = fmaxf(v[16], v[17]), w9 = v[18];
        float x0 = fmaxf(w0, w1), x1 = fmaxf(w2, w3);
        float x2 = fmaxf(w4, w5), x3 = fmaxf(w6, w7);
        float x4 = fmaxf(w8, w9);
        float y0 = fmaxf(x0, x1), y1 = fmaxf(x2, x3);
        float m = fmaxf(fmaxf(y0, y1), x4);

        unsigned msk = 0u;
#pragma unroll
        for (int p = 0; p < TL; p++)
            msk |= (v[p] == m) ? (1u << p) : 0u;
        int best = __ffs(msk) - 1;

        if (lane < TL) mybp[t * 20 + lane] = (unsigned char)best;
        score = m + u;
        u = u_next;
    }

    float fin = (lane < TL) ? score + trans[END_IDX * TL + lane] : -3.4e38f;
    int idx = lane;
#pragma unroll
    for (int off = 16; off > 0; off >>= 1) {
        float of = __shfl_down_sync(0xffffffffu, fin, off);
        int   oi = __shfl_down_sync(0xffffffffu, idx, off);
        if (of > fin || (of == fin && oi < idx)) { fin = of; idx = oi; }
    }

    if (lane == 0) {
        out[b] = fin;
        int cur = idx;
        for (int t = TT - 1; t >= 0; t--) {
            out[BB + b * TT + t] = (float)cur;
            cur = mybp[t * 20 + cur];
        }
    }
}

// =======================================================================
extern "C" void kernel_launch(void* const* d_in, const int* in_sizes, int n_in,
                              void* d_out, int out_size)
{
    const int*   x     = (const int*)d_in[0];
    const float* emb   = (const float*)d_in[1];
    const float* Wif   = (const float*)d_in[2];
    const float* Whf   = (const float*)d_in[3];
    const float* bf    = (const float*)d_in[4];
    const float* Wib   = (const float*)d_in[5];
    const float* Whb   = (const float*)d_in[6];
    const float* bb    = (const float*)d_in[7];
    const float* fc1W  = (const float*)d_in[8];
    const float* fc1b  = (const float*)d_in[9];
    const float* clsW  = (const float*)d_in[10];
    const float* clsb  = (const float*)d_in[11];
    const float* trans = (const float*)d_in[12];
    float* out = (float*)d_out;

    size_t smemB = (2 * 16 * 258 + 256 * 64 + 16 * 68) * sizeof(float);  // ~102 KB
    size_t smemC = (2048 + 4096 + 64 * 128) * sizeof(float);             // 57344 B
    size_t smemD = (4 * 5120 + 384) * sizeof(float) + 4 * 256 * 20;      // ~104 KB
    cudaFuncSetAttribute(lstm_kernel, cudaFuncAttributeMaxDynamicSharedMemorySize, (int)smemB);
    cudaFuncSetAttribute(fc_kernel,   cudaFuncAttributeMaxDynamicSharedMemorySize, (int)smemC);
    cudaFuncSetAttribute(viterbi_kernel, cudaFuncAttributeMaxDynamicSharedMemorySize, (int)smemD);

    dim3 gridA(TT / 4, 32);
    xproj_kernel<<<gridA, 256>>>(x, emb, Wif, bf, Wib, bb);
    lstm_kernel<<<128, 256, smemB>>>(Whf, Whb);
    fc_kernel<<<TT, 256, smemC>>>(fc1W, fc1b, clsW, clsb);
    viterbi_kernel<<<BB / 4, 128, smemD>>>(trans, out);
}

// round 14
// speedup vs baseline: 1.0345x; 1.0345x over previous
#include <cuda_runtime.h>
#include <math.h>

#define BB 64
#define TT 256
#define EE 300
#define HH 256
#define G4H 1024
#define NINTER 128
#define NL 17
#define TL 19
#define START_IDX 17
#define END_IDX 18
#define LOW_POT -10000.0f

typedef unsigned long long ull;

// ---------------- device scratch (static; no allocations allowed) ----------------
__device__ float g_xp[2][TT][G4H][BB];        // x_proj, [dir][t][gate_row][b]
__device__ float g_h[2][2][HH][BB];           // h state double-buffered, [k][b]
__device__ float g_hs[TT][2 * HH][BB];        // hidden history, [t][k][b]
__device__ float g_unary[BB][TT][NL];         // classifier outputs
__device__ unsigned int g_bar_count;
__device__ volatile unsigned int g_bar_gen;
__device__ volatile unsigned int g_flag2[2][64][8];   // per-dir flags, 32B-padded

// ---------------- atomic grid barrier (flag reset at end of lstm) ---------------
__device__ __forceinline__ void grid_barrier(unsigned nb)
{
    __syncthreads();
    if (threadIdx.x == 0) {
        unsigned g = g_bar_gen;
        __threadfence();
        unsigned t = atomicAdd(&g_bar_count, 1u);
        if (t == nb - 1u) {
            g_bar_count = 0u;
            __threadfence();
            g_bar_gen = g + 1u;
        } else {
            while (g_bar_gen == g) { }
        }
        __threadfence();
    }
    __syncthreads();
}

// ---------------- cp.async helpers ----------------
__device__ __forceinline__ void cp_async16(unsigned smem_addr, const void* gptr)
{
    asm volatile("cp.async.cg.shared.global [%0], [%1], 16;\n"
                 :: "r"(smem_addr), "l"(gptr));
}
__device__ __forceinline__ void cp_commit()
{
    asm volatile("cp.async.commit_group;\n");
}
template <int N>
__device__ __forceinline__ void cp_wait()
{
    asm volatile("cp.async.wait_group %0;\n" :: "n"(N));
}

// ---------------- acquire load for flag polling ----------------
__device__ __forceinline__ unsigned ld_acquire_gpu(volatile unsigned* p)
{
    unsigned v;
    asm volatile("ld.acquire.gpu.global.u32 %0, [%1];"
                 : "=r"(v) : "l"((const unsigned*)p) : "memory");
    return v;
}

// ---------------- tf32 helpers (xproj) ----------------
__device__ __forceinline__ unsigned f2tf32(float f)
{
    unsigned u;
    asm("cvt.rna.tf32.f32 %0, %1;" : "=r"(u) : "f"(f));
    return u;
}
__device__ __forceinline__ void mma_tf32(float c[4], const unsigned a[4], const unsigned b[2])
{
    asm volatile("mma.sync.aligned.m16n8k8.row.col.f32.tf32.tf32.f32 "
                 "{%0,%1,%2,%3}, {%4,%5,%6,%7}, {%8,%9}, {%0,%1,%2,%3};"
                 : "+f"(c[0]), "+f"(c[1]), "+f"(c[2]), "+f"(c[3])
                 : "r"(a[0]), "r"(a[1]), "r"(a[2]), "r"(a[3]),
                   "r"(b[0]), "r"(b[1]));
}

// ---------------- packed f32x2 helpers ----------------
__device__ __forceinline__ void fma2(ull& d, ull a, ull b)
{
    asm("fma.rn.f32x2 %0, %1, %2, %0;" : "+l"(d) : "l"(a), "l"(b));
}
__device__ __forceinline__ ull splat2(float x)
{
    ull r;
    asm("mov.b64 %0, {%1, %1};" : "=l"(r) : "r"(__float_as_uint(x)));
    return r;
}
__device__ __forceinline__ ull pack2(float lo, float hi)
{
    ull r;
    asm("mov.b64 %0, {%1, %2};" : "=l"(r) : "r"(__float_as_uint(lo)), "r"(__float_as_uint(hi)));
    return r;
}
__device__ __forceinline__ float2 unpack2(ull v)
{
    unsigned lo, hi;
    asm("mov.b64 {%0, %1}, %2;" : "=r"(lo), "=r"(hi) : "l"(v));
    return make_float2(__uint_as_float(lo), __uint_as_float(hi));
}

// =======================================================================
// Kernel A: embedding gather + x_proj GEMM via 3xTF32 tensor cores.
// 4 token-tiles per block; W chunk conversion amortized. (R8 exact)
// =======================================================================
__global__ void __launch_bounds__(256, 1)
xproj_kernel(const int* __restrict__ x,
             const float* __restrict__ emb,
             const float* __restrict__ Wf,
             const float* __restrict__ bf,
             const float* __restrict__ Wb,
             const float* __restrict__ bb)
{
    __shared__ unsigned sWh[16][72], sWl[16][72];       // W chunk [k][m]
    __shared__ unsigned sEh[4][16][72], sEl[4][16][72]; // E chunks [t][k][n]
    __shared__ int sTok[4][64];

    int tg0 = blockIdx.x * 4;       // 4 consecutive t
    int gt = blockIdx.y;            // 0..31
    int dir = gt >> 4;
    int grow0 = (gt & 15) * 64;
    const float* W = dir ? Wb : Wf;
    const float* bias = dir ? bb : bf;

    int tid = threadIdx.x;
    int warp = tid >> 5, lane = tid & 31;
    int m0 = (warp & 3) * 16;
    int n0 = (warp >> 2) * 32;

    {
        int tt = tid >> 6, b = tid & 63;
        sTok[tt][b] = x[b * TT + (tg0 + tt)];
    }
    __syncthreads();

    float acc[4][4][4];             // [t][n-subtile][C regs]
#pragma unroll
    for (int tt = 0; tt < 4; tt++)
#pragma unroll
        for (int j = 0; j < 4; j++)
#pragma unroll
            for (int c = 0; c < 4; c++) acc[tt][j][c] = 0.f;

    float rw[4], re[16];

#define LOAD_CHUNK(kc)                                                        \
    {                                                                         \
        _Pragma("unroll")                                                     \
        for (int i = 0; i < 4; i++) {                                         \
            int idx = i * 256 + tid;                                          \
            int mm = idx >> 4, kk = (kc) + (idx & 15);                        \
            rw[i] = (kk < EE) ? W[(grow0 + mm) * EE + kk] : 0.f;              \
        }                                                                     \
        _Pragma("unroll")                                                     \
        for (int i = 0; i < 16; i++) {                                        \
            int idx = i * 256 + tid;                                          \
            int tt = idx >> 10, rem = idx & 1023;                             \
            int mm = rem >> 4, kk = (kc) + (rem & 15);                        \
            re[i] = (kk < EE) ? emb[(long)sTok[tt][mm] * EE + kk] : 0.f;      \
        }                                                                     \
    }

    LOAD_CHUNK(0)

    for (int c = 0; c < 19; c++) {
        __syncthreads();
#pragma unroll
        for (int i = 0; i < 4; i++) {
            int idx = i * 256 + tid;
            int mm = idx >> 4, k = idx & 15;
            float fw = rw[i];
            unsigned wh = f2tf32(fw);
            sWh[k][mm] = wh;
            sWl[k][mm] = f2tf32(fw - __uint_as_float(wh));
        }
#pragma unroll
        for (int i = 0; i < 16; i++) {
            int idx = i * 256 + tid;
            int tt = idx >> 10, rem = idx & 1023;
            int mm = rem >> 4, k = rem & 15;
            float fe = re[i];
            unsigned eh = f2tf32(fe);
            sEh[tt][k][mm] = eh;
            sEl[tt][k][mm] = f2tf32(fe - __uint_as_float(eh));
        }
        __syncthreads();
        if (c + 1 < 19) LOAD_CHUNK((c + 1) * 16)

#pragma unroll
        for (int kt = 0; kt < 2; kt++) {
            int ka = kt * 8 + (lane & 3);
            int ra = m0 + (lane >> 2);
            unsigned ah[4], al[4];
            ah[0] = sWh[ka][ra];     al[0] = sWl[ka][ra];
            ah[1] = sWh[ka][ra + 8]; al[1] = sWl[ka][ra + 8];
            ah[2] = sWh[ka + 4][ra];     al[2] = sWl[ka + 4][ra];
            ah[3] = sWh[ka + 4][ra + 8]; al[3] = sWl[ka + 4][ra + 8];
#pragma unroll
            for (int tt = 0; tt < 4; tt++) {
#pragma unroll
                for (int j = 0; j < 4; j++) {
                    int nb = n0 + j * 8 + (lane >> 2);
                    unsigned bh[2], bl[2];
                    bh[0] = sEh[tt][ka][nb];     bl[0] = sEl[tt][ka][nb];
                    bh[1] = sEh[tt][ka + 4][nb]; bl[1] = sEl[tt][ka + 4][nb];
                    mma_tf32(acc[tt][j], ah, bh);
                    mma_tf32(acc[tt][j], ah, bl);
                    mma_tf32(acc[tt][j], al, bh);
                }
            }
        }
    }
#undef LOAD_CHUNK

    int row = m0 + (lane >> 2);
    int colb = (lane & 3) * 2;
    float bv0 = bias[grow0 + row];
    float bv8 = bias[grow0 + row + 8];
#pragma unroll
    for (int tt = 0; tt < 4; tt++) {
        int t = tg0 + tt;
#pragma unroll
        for (int j = 0; j < 4; j++) {
            int col = n0 + j * 8 + colb;
            *(float2*)&g_xp[dir][t][grow0 + row][col] =
                make_float2(acc[tt][j][0] + bv0, acc[tt][j][1] + bv0);
            *(float2*)&g_xp[dir][t][grow0 + row + 8][col] =
                make_float2(acc[tt][j][2] + bv8, acc[tt][j][3] + bv8);
        }
    }
}

// =======================================================================
// Kernel B: persistent BiLSTM (R8/R12 exact). 128 blocks (64/dir) x 256.
// Single 64-flag acquire-poll, 4-deep cp.async quarter pipeline, f32x2
// GEMM, flat smem phase-2, threadfence publish.
// =======================================================================
__global__ void __launch_bounds__(256, 1)
lstm_kernel(const float* __restrict__ Whf,
            const float* __restrict__ Whb)
{
    extern __shared__ float sm[];
    ull*   sW2 = (ull*)sm;                       // 16 x 258 ull pairs (33 KB)
    float* sH  = sm + 2 * 16 * 258;              // 256 x 64 (64 KB)
    float* sG  = sH + 256 * 64;                  // 16 x 68

    int tid = threadIdx.x;
    int bid = blockIdx.x;               // 0..127
    int dir = bid & 1;
    int grp = bid >> 1;                 // 0..63
    int c0 = grp * 4;
    const float* Whh = dir ? Whb : Whf;

    // load + pre-splat 16 W_hh rows (row stride 258 ull, bank-safe)
    for (int idx = tid; idx < 4096; idx += 256) {
        int r = idx >> 8, k = idx & 255;
        int gate = r >> 2, ci = r & 3;
        float w = Whh[(gate * 256 + c0 + ci) * 256 + k];
        sW2[r * 258 + k] = splat2(w);
    }
    // zero-init own slice of h buffer 0
    g_h[dir][0][c0 + (tid >> 6)][tid & 63] = 0.f;
    float c_state = 0.f;

    int r = tid & 15, q = tid >> 4;     // phase-1 mapping: row r of 16, batch quad q
    int wrow = (r >> 2) * 256 + c0 + (r & 3);
    int ci2 = tid >> 6, b2 = tid & 63;  // phase-2 mapping: (col ci2, batch b2)

    unsigned sH_addr = (unsigned)__cvta_generic_to_shared(sH);
    const ull* wr2 = sW2 + r * 258;
    const ulonglong2* hq = (const ulonglong2*)sH + q;

    __syncthreads();
    if (tid == 0) { __threadfence(); g_flag2[dir][grp][0] = 1u; }

    for (int s = 0; s < TT; s++) {
        int t = dir ? (TT - 1 - s) : s;

        // prefetch x_proj tile (independent of flags)
        float4 a = __ldg((const float4*)&g_xp[dir][t][wrow][0] + q);

        // wait: all 64 same-dir blocks have published h generation s
        if (tid < 64) {
            unsigned tgt = (unsigned)(s + 1);
            while (ld_acquire_gpu(&g_flag2[dir][tid][0]) < tgt) { }
        }
        __syncthreads();

        // 4-deep pipelined h broadcast: four 16KB quarters via cp.async
        const float4* hsrc = (const float4*)&g_h[dir][s & 1][0][0];
#pragma unroll
        for (int g = 0; g < 4; g++) {
#pragma unroll
            for (int i = g * 4; i < g * 4 + 4; i++)
                cp_async16(sH_addr + (unsigned)((i * 256 + tid) * 16), hsrc + i * 256 + tid);
            cp_commit();
        }

        ull acc0 = pack2(a.x, a.y);
        ull acc1 = pack2(a.z, a.w);

        cp_wait<3>();
        __syncthreads();
#pragma unroll 8
        for (int k = 0; k < 64; k++) {
            ull ww = wr2[k];
            ulonglong2 h2 = hq[k * 16];
            fma2(acc0, ww, h2.x);
            fma2(acc1, ww, h2.y);
        }
        cp_wait<2>();
        __syncthreads();
#pragma unroll 8
        for (int k = 64; k < 128; k++) {
            ull ww = wr2[k];
            ulonglong2 h2 = hq[k * 16];
            fma2(acc0, ww, h2.x);
            fma2(acc1, ww, h2.y);
        }
        cp_wait<1>();
        __syncthreads();
#pragma unroll 8
        for (int k = 128; k < 192; k++) {
            ull ww = wr2[k];
            ulonglong2 h2 = hq[k * 16];
            fma2(acc0, ww, h2.x);
            fma2(acc1, ww, h2.y);
        }
        cp_wait<0>();
        __syncthreads();
#pragma unroll 8
        for (int k = 192; k < 256; k++) {
            ull ww = wr2[k];
            ulonglong2 h2 = hq[k * 16];
            fma2(acc0, ww, h2.x);
            fma2(acc1, ww, h2.y);
        }
        {
            float2 v0 = unpack2(acc0), v1 = unpack2(acc1);
            *(float4*)&sG[r * 68 + q * 4] = make_float4(v0.x, v0.y, v1.x, v1.y);
        }
        __syncthreads();

        // phase 2: gate nonlinearity + state update for (col c0+ci2, batch b2)
        float gi = sG[(0 + ci2) * 68 + b2];
        float gf = sG[(4 + ci2) * 68 + b2];
        float gg = sG[(8 + ci2) * 68 + b2];
        float go = sG[(12 + ci2) * 68 + b2];
        float i_s = 1.f / (1.f + __expf(-gi));
        float f_s = 1.f / (1.f + __expf(-gf));
        float o_s = 1.f / (1.f + __expf(-go));
        float c_new = f_s * c_state + i_s * tanhf(gg);
        c_state = c_new;
        float h_new = o_s * tanhf(c_new);

        g_h[dir][(s + 1) & 1][c0 + ci2][b2] = h_new;        // coalesced
        g_hs[t][dir * 256 + c0 + ci2][b2] = h_new;          // coalesced ([t][k][b])

        __syncthreads();
        if (tid == 0) { __threadfence(); g_flag2[dir][grp][0] = (unsigned)(s + 2); }
    }

    // all blocks past every poll, then reset flags for the next graph replay
    grid_barrier(128u);
    if (tid == 0) g_flag2[dir][grp][0] = 0u;
}

// =======================================================================
// Kernel C: fc1 + ReLU + classifier -> unary. 256 blocks (one t each),
// f32x2 packed math. (R8 exact)
// =======================================================================
__global__ void fc_kernel(const float* __restrict__ fc1W,
                          const float* __restrict__ fc1b,
                          const float* __restrict__ clsW,
                          const float* __restrict__ clsb)
{
    extern __shared__ float sm[];
    float* sA = sm;                  // 32 x 64
    float* sB = sm + 2048;           // 32 x 128
    float* sI = sm + 6144;           // 64 x 128

    int tid = threadIdx.x;
    int t = blockIdx.x;

    int tr = tid >> 4, tn = tid & 15;
    int r0 = tr * 4, n0 = tn * 8;

    ull acc[4][4];
#pragma unroll
    for (int i = 0; i < 4; i++)
#pragma unroll
        for (int j = 0; j < 4; j++) acc[i][j] = 0ull;

    for (int kc = 0; kc < 512; kc += 32) {
        __syncthreads();
        for (int idx = tid; idx < 512; idx += 256) {
            int k = idx >> 4, b4 = idx & 15;
            *(float4*)&sA[k * 64 + b4 * 4] =
                *(const float4*)&g_hs[t][kc + k][b4 * 4];
        }
        for (int idx = tid; idx < 1024; idx += 256) {
            int n = idx >> 3, kq = idx & 7;
            float4 v = *(const float4*)&fc1W[n * 512 + kc + kq * 4];
            sB[(kq * 4 + 0) * 128 + n] = v.x;
            sB[(kq * 4 + 1) * 128 + n] = v.y;
            sB[(kq * 4 + 2) * 128 + n] = v.z;
            sB[(kq * 4 + 3) * 128 + n] = v.w;
        }
        __syncthreads();
#pragma unroll
        for (int k = 0; k < 32; k++) {
            float4 a4 = *(const float4*)&sA[k * 64 + r0];
            ull aw[4] = {splat2(a4.x), splat2(a4.y), splat2(a4.z), splat2(a4.w)};
            ulonglong2 bA = *(const ulonglong2*)&sB[k * 128 + n0];
            ulonglong2 bC = *(const ulonglong2*)&sB[k * 128 + n0 + 4];
#pragma unroll
            for (int i = 0; i < 4; i++) {
                fma2(acc[i][0], aw[i], bA.x);
                fma2(acc[i][1], aw[i], bA.y);
                fma2(acc[i][2], aw[i], bC.x);
                fma2(acc[i][3], aw[i], bC.y);
            }
        }
    }

#pragma unroll
    for (int i = 0; i < 4; i++)
#pragma unroll
        for (int j = 0; j < 4; j++) {
            float2 v = unpack2(acc[i][j]);
            int n = n0 + j * 2;
            sI[(r0 + i) * 128 + n]     = fmaxf(v.x + fc1b[n], 0.f);
            sI[(r0 + i) * 128 + n + 1] = fmaxf(v.y + fc1b[n + 1], 0.f);
        }
    __syncthreads();

    float* sCW = sA;
    for (int idx = tid; idx < NL * 128; idx += 256) {
        int l = idx >> 7, k = idx & 127;
        sCW[l * 129 + k] = clsW[idx];
    }
    __syncthreads();

    for (int oi = tid; oi < 64 * NL; oi += 256) {
        int b = oi / NL, l = oi % NL;
        const float* ip = &sI[b * 128];
        const float* wp = &sCW[l * 129];
        float s = 0.f;
#pragma unroll 8
        for (int k = 0; k < 128; k++) s += ip[k] * wp[k];
        g_unary[b][t][l] = s + clsb[l];
    }
}

// =======================================================================
// Kernel D: Viterbi decode. 16 blocks x 128 threads, 1 warp per batch.
// Unary staged in smem per warp (one-time coalesced load) -> in-loop
// access is LDS, hidden by 1-step prefetch. (R13 exact — measured 65.6us)
// =======================================================================
__global__ void viterbi_kernel(const float* __restrict__ trans,
                               float* __restrict__ out)
{
    extern __shared__ float vsm[];
    float* sU = vsm;                                   // [4][256*20] floats
    float* tpn_s = vsm + 4 * 5120;                     // [19][20]
    unsigned char* bps = (unsigned char*)(vsm + 4 * 5120 + 384);  // [4][256][20]

    int tid = threadIdx.x;
    int warp = tid >> 5, lane = tid & 31;
    int b = blockIdx.x * 4 + warp;
    float* sUw = sU + warp * 5120;
    unsigned char* mybp = bps + warp * (256 * 20);

    // stage this batch's unary into smem (coalesced 4352-float copy)
    {
        const float* gu = &g_unary[b][0][0];
        for (int i = lane; i < TT * NL; i += 32)
            sUw[(i / NL) * 20 + (i % NL)] = __ldg(&gu[i]);
    }
    for (int i = tid; i < TL * TL; i += 128) {
        int p = i / TL, n = i % TL;
        tpn_s[p * 20 + n] = trans[n * TL + p];
    }
    __syncthreads();

    float tp[TL];
#pragma unroll
    for (int p = 0; p < TL; p++)
        tp[p] = (lane < TL) ? tpn_s[p * 20 + lane] : LOW_POT;

    float score = (lane == START_IDX) ? 0.f : LOW_POT;
    float u = (lane < NL) ? sUw[lane] : LOW_POT;

    for (int t = 0; t < TT; t++) {
        float u_next = (t + 1 < TT && lane < NL) ? sUw[(t + 1) * 20 + lane] : LOW_POT;

        float v[TL];
#pragma unroll
        for (int p = 0; p < TL; p++)
            v[p] = __shfl_sync(0xffffffffu, score, p) + tp[p];

        float w0 = fmaxf(v[0], v[1]),   w1 = fmaxf(v[2], v[3]);
        float w2 = fmaxf(v[4], v[5]),   w3 = fmaxf(v[6], v[7]);
        float w4 = fmaxf(v[8], v[9]),   w5 = fmaxf(v[10], v[11]);
        float w6 = fmaxf(v[12], v[13]), w7 = fmaxf(v[14], v[15]);
        float w8 = fmaxf(v[16], v[17]), w9 = v[18];
        float x0 = fmaxf(w0, w1), x1 = fmaxf(w2, w3);
        float x2 = fmaxf(w4, w5), x3 = fmaxf(w6, w7);
        float x4 = fmaxf(w8, w9);
        float y0 = fmaxf(x0, x1), y1 = fmaxf(x2, x3);
        float m = fmaxf(fmaxf(y0, y1), x4);

        unsigned msk = 0u;
#pragma unroll
        for (int p = 0; p < TL; p++)
            msk |= (v[p] == m) ? (1u << p) : 0u;
        int best = __ffs(msk) - 1;

        if (lane < TL) mybp[t * 20 + lane] = (unsigned char)best;
        score = m + u;
        u = u_next;
    }

    float fin = (lane < TL) ? score + trans[END_IDX * TL + lane] : -3.4e38f;
    int idx = lane;
#pragma unroll
    for (int off = 16; off > 0; off >>= 1) {
        float of = __shfl_down_sync(0xffffffffu, fin, off);
        int   oi = __shfl_down_sync(0xffffffffu, idx, off);
        if (of > fin || (of == fin && oi < idx)) { fin = of; idx = oi; }
    }

    if (lane == 0) {
        out[b] = fin;
        int cur = idx;
        for (int t = TT - 1; t >= 0; t--) {
            out[BB + b * TT + t] = (float)cur;
            cur = mybp[t * 20 + cur];
        }
    }
}

// =======================================================================
extern "C" void kernel_launch(void* const* d_in, const int* in_sizes, int n_in,
                              void* d_out, int out_size)
{
    const int*   x     = (const int*)d_in[0];
    const float* emb   = (const float*)d_in[1];
    const float* Wif   = (const float*)d_in[2];
    const float* Whf   = (const float*)d_in[3];
    const float* bf    = (const float*)d_in[4];
    const float* Wib   = (const float*)d_in[5];
    const float* Whb   = (const float*)d_in[6];
    const float* bb    = (const float*)d_in[7];
    const float* fc1W  = (const float*)d_in[8];
    const float* fc1b  = (const float*)d_in[9];
    const float* clsW  = (const float*)d_in[10];
    const float* clsb  = (const float*)d_in[11];
    const float* trans = (const float*)d_in[12];
    float* out = (float*)d_out;

    size_t smemB = (2 * 16 * 258 + 256 * 64 + 16 * 68) * sizeof(float);  // ~102 KB
    size_t smemC = (2048 + 4096 + 64 * 128) * sizeof(float);             // 57344 B
    size_t smemD = (4 * 5120 + 384) * sizeof(float) + 4 * 256 * 20;      // ~104 KB
    cudaFuncSetAttribute(lstm_kernel, cudaFuncAttributeMaxDynamicSharedMemorySize, (int)smemB);
    cudaFuncSetAttribute(fc_kernel,   cudaFuncAttributeMaxDynamicSharedMemorySize, (int)smemC);
    cudaFuncSetAttribute(viterbi_kernel, cudaFuncAttributeMaxDynamicSharedMemorySize, (int)smemD);

    dim3 gridA(TT / 4, 32);
    xproj_kernel<<<gridA, 256>>>(x, emb, Wif, bf, Wib, bb);
    lstm_kernel<<<128, 256, smemB>>>(Whf, Whb);
    fc_kernel<<<TT, 256, smemC>>>(fc1W, fc1b, clsW, clsb);
    viterbi_kernel<<<BB / 4, 128, smemD>>>(trans, out);
}

// round 15
// speedup vs baseline: 1.0390x; 1.0044x over previous
#include <cuda_runtime.h>
#include <math.h>

#define BB 64
#define TT 256
#define EE 300
#define HH 256
#define G4H 1024
#define NINTER 128
#define NL 17
#define TL 19
#define START_IDX 17
#define END_IDX 18
#define LOW_POT -10000.0f

typedef unsigned long long ull;

// ---------------- device scratch (static; no allocations allowed) ----------------
__device__ float g_xp[2][TT][G4H][BB];        // x_proj, [dir][t][gate_row][b]
__device__ float g_h[2][2][HH][BB];           // h state double-buffered, [k][b]
__device__ float g_hs[TT][2 * HH][BB];        // hidden history, [t][k][b]
__device__ float g_unary[BB][TT][NL];         // classifier outputs
__device__ unsigned int g_bar_count;
__device__ volatile unsigned int g_bar_gen;
__device__ volatile unsigned int g_flag2[2][64][8];   // per-dir flags, 32B-padded

// ---------------- atomic grid barrier (flag reset at end of lstm) ---------------
__device__ __forceinline__ void grid_barrier(unsigned nb)
{
    __syncthreads();
    if (threadIdx.x == 0) {
        unsigned g = g_bar_gen;
        __threadfence();
        unsigned t = atomicAdd(&g_bar_count, 1u);
        if (t == nb - 1u) {
            g_bar_count = 0u;
            __threadfence();
            g_bar_gen = g + 1u;
        } else {
            while (g_bar_gen == g) { }
        }
        __threadfence();
    }
    __syncthreads();
}

// ---------------- cp.async helpers ----------------
__device__ __forceinline__ void cp_async16(unsigned smem_addr, const void* gptr)
{
    asm volatile("cp.async.cg.shared.global [%0], [%1], 16;\n"
                 :: "r"(smem_addr), "l"(gptr));
}
__device__ __forceinline__ void cp_commit()
{
    asm volatile("cp.async.commit_group;\n");
}
template <int N>
__device__ __forceinline__ void cp_wait()
{
    asm volatile("cp.async.wait_group %0;\n" :: "n"(N));
}

// ---------------- acquire load for flag polling ----------------
__device__ __forceinline__ unsigned ld_acquire_gpu(volatile unsigned* p)
{
    unsigned v;
    asm volatile("ld.acquire.gpu.global.u32 %0, [%1];"
                 : "=r"(v) : "l"((const unsigned*)p) : "memory");
    return v;
}

// ---------------- tf32 helpers (xproj) ----------------
__device__ __forceinline__ unsigned f2tf32(float f)
{
    unsigned u;
    asm("cvt.rna.tf32.f32 %0, %1;" : "=r"(u) : "f"(f));
    return u;
}
__device__ __forceinline__ void mma_tf32(float c[4], const unsigned a[4], const unsigned b[2])
{
    asm volatile("mma.sync.aligned.m16n8k8.row.col.f32.tf32.tf32.f32 "
                 "{%0,%1,%2,%3}, {%4,%5,%6,%7}, {%8,%9}, {%0,%1,%2,%3};"
                 : "+f"(c[0]), "+f"(c[1]), "+f"(c[2]), "+f"(c[3])
                 : "r"(a[0]), "r"(a[1]), "r"(a[2]), "r"(a[3]),
                   "r"(b[0]), "r"(b[1]));
}

// ---------------- packed f32x2 helpers ----------------
__device__ __forceinline__ void fma2(ull& d, ull a, ull b)
{
    asm("fma.rn.f32x2 %0, %1, %2, %0;" : "+l"(d) : "l"(a), "l"(b));
}
__device__ __forceinline__ ull splat2(float x)
{
    ull r;
    asm("mov.b64 %0, {%1, %1};" : "=l"(r) : "r"(__float_as_uint(x)));
    return r;
}
__device__ __forceinline__ ull pack2(float lo, float hi)
{
    ull r;
    asm("mov.b64 %0, {%1, %2};" : "=l"(r) : "r"(__float_as_uint(lo)), "r"(__float_as_uint(hi)));
    return r;
}
__device__ __forceinline__ float2 unpack2(ull v)
{
    unsigned lo, hi;
    asm("mov.b64 {%0, %1}, %2;" : "=r"(lo), "=r"(hi) : "l"(v));
    return make_float2(__uint_as_float(lo), __uint_as_float(hi));
}

// =======================================================================
// Kernel A: embedding gather + x_proj GEMM via 3xTF32 tensor cores.
// 4 token-tiles per block; W chunk conversion amortized. (R8 exact)
// =======================================================================
__global__ void __launch_bounds__(256, 1)
xproj_kernel(const int* __restrict__ x,
             const float* __restrict__ emb,
             const float* __restrict__ Wf,
             const float* __restrict__ bf,
             const float* __restrict__ Wb,
             const float* __restrict__ bb)
{
    __shared__ unsigned sWh[16][72], sWl[16][72];       // W chunk [k][m]
    __shared__ unsigned sEh[4][16][72], sEl[4][16][72]; // E chunks [t][k][n]
    __shared__ int sTok[4][64];

    int tg0 = blockIdx.x * 4;       // 4 consecutive t
    int gt = blockIdx.y;            // 0..31
    int dir = gt >> 4;
    int grow0 = (gt & 15) * 64;
    const float* W = dir ? Wb : Wf;
    const float* bias = dir ? bb : bf;

    int tid = threadIdx.x;
    int warp = tid >> 5, lane = tid & 31;
    int m0 = (warp & 3) * 16;
    int n0 = (warp >> 2) * 32;

    {
        int tt = tid >> 6, b = tid & 63;
        sTok[tt][b] = x[b * TT + (tg0 + tt)];
    }
    __syncthreads();

    float acc[4][4][4];             // [t][n-subtile][C regs]
#pragma unroll
    for (int tt = 0; tt < 4; tt++)
#pragma unroll
        for (int j = 0; j < 4; j++)
#pragma unroll
            for (int c = 0; c < 4; c++) acc[tt][j][c] = 0.f;

    float rw[4], re[16];

#define LOAD_CHUNK(kc)                                                        \
    {                                                                         \
        _Pragma("unroll")                                                     \
        for (int i = 0; i < 4; i++) {                                         \
            int idx = i * 256 + tid;                                          \
            int mm = idx >> 4, kk = (kc) + (idx & 15);                        \
            rw[i] = (kk < EE) ? W[(grow0 + mm) * EE + kk] : 0.f;              \
        }                                                                     \
        _Pragma("unroll")                                                     \
        for (int i = 0; i < 16; i++) {                                        \
            int idx = i * 256 + tid;                                          \
            int tt = idx >> 10, rem = idx & 1023;                             \
            int mm = rem >> 4, kk = (kc) + (rem & 15);                        \
            re[i] = (kk < EE) ? emb[(long)sTok[tt][mm] * EE + kk] : 0.f;      \
        }                                                                     \
    }

    LOAD_CHUNK(0)

    for (int c = 0; c < 19; c++) {
        __syncthreads();
#pragma unroll
        for (int i = 0; i < 4; i++) {
            int idx = i * 256 + tid;
            int mm = idx >> 4, k = idx & 15;
            float fw = rw[i];
            unsigned wh = f2tf32(fw);
            sWh[k][mm] = wh;
            sWl[k][mm] = f2tf32(fw - __uint_as_float(wh));
        }
#pragma unroll
        for (int i = 0; i < 16; i++) {
            int idx = i * 256 + tid;
            int tt = idx >> 10, rem = idx & 1023;
            int mm = rem >> 4, k = rem & 15;
            float fe = re[i];
            unsigned eh = f2tf32(fe);
            sEh[tt][k][mm] = eh;
            sEl[tt][k][mm] = f2tf32(fe - __uint_as_float(eh));
        }
        __syncthreads();
        if (c + 1 < 19) LOAD_CHUNK((c + 1) * 16)

#pragma unroll
        for (int kt = 0; kt < 2; kt++) {
            int ka = kt * 8 + (lane & 3);
            int ra = m0 + (lane >> 2);
            unsigned ah[4], al[4];
            ah[0] = sWh[ka][ra];     al[0] = sWl[ka][ra];
            ah[1] = sWh[ka][ra + 8]; al[1] = sWl[ka][ra + 8];
            ah[2] = sWh[ka + 4][ra];     al[2] = sWl[ka + 4][ra];
            ah[3] = sWh[ka + 4][ra + 8]; al[3] = sWl[ka + 4][ra + 8];
#pragma unroll
            for (int tt = 0; tt < 4; tt++) {
#pragma unroll
                for (int j = 0; j < 4; j++) {
                    int nb = n0 + j * 8 + (lane >> 2);
                    unsigned bh[2], bl[2];
                    bh[0] = sEh[tt][ka][nb];     bl[0] = sEl[tt][ka][nb];
                    bh[1] = sEh[tt][ka + 4][nb]; bl[1] = sEl[tt][ka + 4][nb];
                    mma_tf32(acc[tt][j], ah, bh);
                    mma_tf32(acc[tt][j], ah, bl);
                    mma_tf32(acc[tt][j], al, bh);
                }
            }
        }
    }
#undef LOAD_CHUNK

    int row = m0 + (lane >> 2);
    int colb = (lane & 3) * 2;
    float bv0 = bias[grow0 + row];
    float bv8 = bias[grow0 + row + 8];
#pragma unroll
    for (int tt = 0; tt < 4; tt++) {
        int t = tg0 + tt;
#pragma unroll
        for (int j = 0; j < 4; j++) {
            int col = n0 + j * 8 + colb;
            *(float2*)&g_xp[dir][t][grow0 + row][col] =
                make_float2(acc[tt][j][0] + bv0, acc[tt][j][1] + bv0);
            *(float2*)&g_xp[dir][t][grow0 + row + 8][col] =
                make_float2(acc[tt][j][2] + bv8, acc[tt][j][3] + bv8);
        }
    }
}

// =======================================================================
// Kernel B: persistent BiLSTM (R8 structure). 128 blocks (64/dir) x 256.
// Single 64-flag acquire-poll, 4-deep cp.async quarter pipeline, f32x2
// GEMM, flat smem phase-2. ONE change vs R14: g_hs history store moved
// AFTER the flag publish (off the serial inter-block path; fc consumes it
// only after kernel end).
// =======================================================================
__global__ void __launch_bounds__(256, 1)
lstm_kernel(const float* __restrict__ Whf,
            const float* __restrict__ Whb)
{
    extern __shared__ float sm[];
    ull*   sW2 = (ull*)sm;                       // 16 x 258 ull pairs (33 KB)
    float* sH  = sm + 2 * 16 * 258;              // 256 x 64 (64 KB)
    float* sG  = sH + 256 * 64;                  // 16 x 68

    int tid = threadIdx.x;
    int bid = blockIdx.x;               // 0..127
    int dir = bid & 1;
    int grp = bid >> 1;                 // 0..63
    int c0 = grp * 4;
    const float* Whh = dir ? Whb : Whf;

    // load + pre-splat 16 W_hh rows (row stride 258 ull, bank-safe)
    for (int idx = tid; idx < 4096; idx += 256) {
        int r = idx >> 8, k = idx & 255;
        int gate = r >> 2, ci = r & 3;
        float w = Whh[(gate * 256 + c0 + ci) * 256 + k];
        sW2[r * 258 + k] = splat2(w);
    }
    // zero-init own slice of h buffer 0
    g_h[dir][0][c0 + (tid >> 6)][tid & 63] = 0.f;
    float c_state = 0.f;

    int r = tid & 15, q = tid >> 4;     // phase-1 mapping: row r of 16, batch quad q
    int wrow = (r >> 2) * 256 + c0 + (r & 3);
    int ci2 = tid >> 6, b2 = tid & 63;  // phase-2 mapping: (col ci2, batch b2)

    unsigned sH_addr = (unsigned)__cvta_generic_to_shared(sH);
    const ull* wr2 = sW2 + r * 258;
    const ulonglong2* hq = (const ulonglong2*)sH + q;

    __syncthreads();
    if (tid == 0) { __threadfence(); g_flag2[dir][grp][0] = 1u; }

    for (int s = 0; s < TT; s++) {
        int t = dir ? (TT - 1 - s) : s;

        // prefetch x_proj tile (independent of flags)
        float4 a = __ldg((const float4*)&g_xp[dir][t][wrow][0] + q);

        // wait: all 64 same-dir blocks have published h generation s
        if (tid < 64) {
            unsigned tgt = (unsigned)(s + 1);
            while (ld_acquire_gpu(&g_flag2[dir][tid][0]) < tgt) { }
        }
        __syncthreads();

        // 4-deep pipelined h broadcast: four 16KB quarters via cp.async
        const float4* hsrc = (const float4*)&g_h[dir][s & 1][0][0];
#pragma unroll
        for (int g = 0; g < 4; g++) {
#pragma unroll
            for (int i = g * 4; i < g * 4 + 4; i++)
                cp_async16(sH_addr + (unsigned)((i * 256 + tid) * 16), hsrc + i * 256 + tid);
            cp_commit();
        }

        ull acc0 = pack2(a.x, a.y);
        ull acc1 = pack2(a.z, a.w);

        cp_wait<3>();
        __syncthreads();
#pragma unroll 8
        for (int k = 0; k < 64; k++) {
            ull ww = wr2[k];
            ulonglong2 h2 = hq[k * 16];
            fma2(acc0, ww, h2.x);
            fma2(acc1, ww, h2.y);
        }
        cp_wait<2>();
        __syncthreads();
#pragma unroll 8
        for (int k = 64; k < 128; k++) {
            ull ww = wr2[k];
            ulonglong2 h2 = hq[k * 16];
            fma2(acc0, ww, h2.x);
            fma2(acc1, ww, h2.y);
        }
        cp_wait<1>();
        __syncthreads();
#pragma unroll 8
        for (int k = 128; k < 192; k++) {
            ull ww = wr2[k];
            ulonglong2 h2 = hq[k * 16];
            fma2(acc0, ww, h2.x);
            fma2(acc1, ww, h2.y);
        }
        cp_wait<0>();
        __syncthreads();
#pragma unroll 8
        for (int k = 192; k < 256; k++) {
            ull ww = wr2[k];
            ulonglong2 h2 = hq[k * 16];
            fma2(acc0, ww, h2.x);
            fma2(acc1, ww, h2.y);
        }
        {
            float2 v0 = unpack2(acc0), v1 = unpack2(acc1);
            *(float4*)&sG[r * 68 + q * 4] = make_float4(v0.x, v0.y, v1.x, v1.y);
        }
        __syncthreads();

        // phase 2: gate nonlinearity + state update for (col c0+ci2, batch b2)
        float gi = sG[(0 + ci2) * 68 + b2];
        float gf = sG[(4 + ci2) * 68 + b2];
        float gg = sG[(8 + ci2) * 68 + b2];
        float go = sG[(12 + ci2) * 68 + b2];
        float i_s = 1.f / (1.f + __expf(-gi));
        float f_s = 1.f / (1.f + __expf(-gf));
        float o_s = 1.f / (1.f + __expf(-go));
        float c_new = f_s * c_state + i_s * tanhf(gg);
        c_state = c_new;
        float h_new = o_s * tanhf(c_new);

        // critical-path publish: only g_h before the fence
        g_h[dir][(s + 1) & 1][c0 + ci2][b2] = h_new;        // coalesced

        __syncthreads();
        if (tid == 0) { __threadfence(); g_flag2[dir][grp][0] = (unsigned)(s + 2); }

        // history store OFF the serial path (consumed only after kernel end)
        g_hs[t][dir * 256 + c0 + ci2][b2] = h_new;          // coalesced ([t][k][b])
    }

    // all blocks past every poll, then reset flags for the next graph replay
    grid_barrier(128u);
    if (tid == 0) g_flag2[dir][grp][0] = 0u;
}

// =======================================================================
// Kernel C: fc1 + ReLU + classifier -> unary. 256 blocks (one t each),
// f32x2 packed math. (R8 exact)
// =======================================================================
__global__ void fc_kernel(const float* __restrict__ fc1W,
                          const float* __restrict__ fc1b,
                          const float* __restrict__ clsW,
                          const float* __restrict__ clsb)
{
    extern __shared__ float sm[];
    float* sA = sm;                  // 32 x 64
    float* sB = sm + 2048;           // 32 x 128
    float* sI = sm + 6144;           // 64 x 128

    int tid = threadIdx.x;
    int t = blockIdx.x;

    int tr = tid >> 4, tn = tid & 15;
    int r0 = tr * 4, n0 = tn * 8;

    ull acc[4][4];
#pragma unroll
    for (int i = 0; i < 4; i++)
#pragma unroll
        for (int j = 0; j < 4; j++) acc[i][j] = 0ull;

    for (int kc = 0; kc < 512; kc += 32) {
        __syncthreads();
        for (int idx = tid; idx < 512; idx += 256) {
            int k = idx >> 4, b4 = idx & 15;
            *(float4*)&sA[k * 64 + b4 * 4] =
                *(const float4*)&g_hs[t][kc + k][b4 * 4];
        }
        for (int idx = tid; idx < 1024; idx += 256) {
            int n = idx >> 3, kq = idx & 7;
            float4 v = *(const float4*)&fc1W[n * 512 + kc + kq * 4];
            sB[(kq * 4 + 0) * 128 + n] = v.x;
            sB[(kq * 4 + 1) * 128 + n] = v.y;
            sB[(kq * 4 + 2) * 128 + n] = v.z;
            sB[(kq * 4 + 3) * 128 + n] = v.w;
        }
        __syncthreads();
#pragma unroll
        for (int k = 0; k < 32; k++) {
            float4 a4 = *(const float4*)&sA[k * 64 + r0];
            ull aw[4] = {splat2(a4.x), splat2(a4.y), splat2(a4.z), splat2(a4.w)};
            ulonglong2 bA = *(const ulonglong2*)&sB[k * 128 + n0];
            ulonglong2 bC = *(const ulonglong2*)&sB[k * 128 + n0 + 4];
#pragma unroll
            for (int i = 0; i < 4; i++) {
                fma2(acc[i][0], aw[i], bA.x);
                fma2(acc[i][1], aw[i], bA.y);
                fma2(acc[i][2], aw[i], bC.x);
                fma2(acc[i][3], aw[i], bC.y);
            }
        }
    }

#pragma unroll
    for (int i = 0; i < 4; i++)
#pragma unroll
        for (int j = 0; j < 4; j++) {
            float2 v = unpack2(acc[i][j]);
            int n = n0 + j * 2;
            sI[(r0 + i) * 128 + n]     = fmaxf(v.x + fc1b[n], 0.f);
            sI[(r0 + i) * 128 + n + 1] = fmaxf(v.y + fc1b[n + 1], 0.f);
        }
    __syncthreads();

    float* sCW = sA;
    for (int idx = tid; idx < NL * 128; idx += 256) {
        int l = idx >> 7, k = idx & 127;
        sCW[l * 129 + k] = clsW[idx];
    }
    __syncthreads();

    for (int oi = tid; oi < 64 * NL; oi += 256) {
        int b = oi / NL, l = oi % NL;
        const float* ip = &sI[b * 128];
        const float* wp = &sCW[l * 129];
        float s = 0.f;
#pragma unroll 8
        for (int k = 0; k < 128; k++) s += ip[k] * wp[k];
        g_unary[b][t][l] = s + clsb[l];
    }
}

// =======================================================================
// Kernel D: Viterbi decode. 16 blocks x 128 threads, 1 warp per batch.
// Unary staged in smem per warp. (R13 exact — measured 65.6us)
// =======================================================================
__global__ void viterbi_kernel(const float* __restrict__ trans,
                               float* __restrict__ out)
{
    extern __shared__ float vsm[];
    float* sU = vsm;                                   // [4][256*20] floats
    float* tpn_s = vsm + 4 * 5120;                     // [19][20]
    unsigned char* bps = (unsigned char*)(vsm + 4 * 5120 + 384);  // [4][256][20]

    int tid = threadIdx.x;
    int warp = tid >> 5, lane = tid & 31;
    int b = blockIdx.x * 4 + warp;
    float* sUw = sU + warp * 5120;
    unsigned char* mybp = bps + warp * (256 * 20);

    // stage this batch's unary into smem (coalesced 4352-float copy)
    {
        const float* gu = &g_unary[b][0][0];
        for (int i = lane; i < TT * NL; i += 32)
            sUw[(i / NL) * 20 + (i % NL)] = __ldg(&gu[i]);
    }
    for (int i = tid; i < TL * TL; i += 128) {
        int p = i / TL, n = i % TL;
        tpn_s[p * 20 + n] = trans[n * TL + p];
    }
    __syncthreads();

    float tp[TL];
#pragma unroll
    for (int p = 0; p < TL; p++)
        tp[p] = (lane < TL) ? tpn_s[p * 20 + lane] : LOW_POT;

    float score = (lane == START_IDX) ? 0.f : LOW_POT;
    float u = (lane < NL) ? sUw[lane] : LOW_POT;

    for (int t = 0; t < TT; t++) {
        float u_next = (t + 1 < TT && lane < NL) ? sUw[(t + 1) * 20 + lane] : LOW_POT;

        float v[TL];
#pragma unroll
        for (int p = 0; p < TL; p++)
            v[p] = __shfl_sync(0xffffffffu, score, p) + tp[p];

        float w0 = fmaxf(v[0], v[1]),   w1 = fmaxf(v[2], v[3]);
        float w2 = fmaxf(v[4], v[5]),   w3 = fmaxf(v[6], v[7]);
        float w4 = fmaxf(v[8], v[9]),   w5 = fmaxf(v[10], v[11]);
        float w6 = fmaxf(v[12], v[13]), w7 = fmaxf(v[14], v[15]);
        float w8 = fmaxf(v[16], v[17]), w9 = v[18];
        float x0 = fmaxf(w0, w1), x1 = fmaxf(w2, w3);
        float x2 = fmaxf(w4, w5), x3 = fmaxf(w6, w7);
        float x4 = fmaxf(w8, w9);
        float y0 = fmaxf(x0, x1), y1 = fmaxf(x2, x3);
        float m = fmaxf(fmaxf(y0, y1), x4);

        unsigned msk = 0u;
#pragma unroll
        for (int p = 0; p < TL; p++)
            msk |= (v[p] == m) ? (1u << p) : 0u;
        int best = __ffs(msk) - 1;

        if (lane < TL) mybp[t * 20 + lane] = (unsigned char)best;
        score = m + u;
        u = u_next;
    }

    float fin = (lane < TL) ? score + trans[END_IDX * TL + lane] : -3.4e38f;
    int idx = lane;
#pragma unroll
    for (int off = 16; off > 0; off >>= 1) {
        float of = __shfl_down_sync(0xffffffffu, fin, off);
        int   oi = __shfl_down_sync(0xffffffffu, idx, off);
        if (of > fin || (of == fin && oi < idx)) { fin = of; idx = oi; }
    }

    if (lane == 0) {
        out[b] = fin;
        int cur = idx;
        for (int t = TT - 1; t >= 0; t--) {
            out[BB + b * TT + t] = (float)cur;
            cur = mybp[t * 20 + cur];
        }
    }
}

// =======================================================================
extern "C" void kernel_launch(void* const* d_in, const int* in_sizes, int n_in,
                              void* d_out, int out_size)
{
    const int*   x     = (const int*)d_in[0];
    const float* emb   = (const float*)d_in[1];
    const float* Wif   = (const float*)d_in[2];
    const float* Whf   = (const float*)d_in[3];
    const float* bf    = (const float*)d_in[4];
    const float* Wib   = (const float*)d_in[5];
    const float* Whb   = (const float*)d_in[6];
    const float* bb    = (const float*)d_in[7];
    const float* fc1W  = (const float*)d_in[8];
    const float* fc1b  = (const float*)d_in[9];
    const float* clsW  = (const float*)d_in[10];
    const float* clsb  = (const float*)d_in[11];
    const float* trans = (const float*)d_in[12];
    float* out = (float*)d_out;

    size_t smemB = (2 * 16 * 258 + 256 * 64 + 16 * 68) * sizeof(float);  // ~102 KB
    size_t smemC = (2048 + 4096 + 64 * 128) * sizeof(float);             // 57344 B
    size_t smemD = (4 * 5120 + 384) * sizeof(float) + 4 * 256 * 20;      // ~104 KB
    cudaFuncSetAttribute(lstm_kernel, cudaFuncAttributeMaxDynamicSharedMemorySize, (int)smemB);
    cudaFuncSetAttribute(fc_kernel,   cudaFuncAttributeMaxDynamicSharedMemorySize, (int)smemC);
    cudaFuncSetAttribute(viterbi_kernel, cudaFuncAttributeMaxDynamicSharedMemorySize, (int)smemD);

    dim3 gridA(TT / 4, 32);
    xproj_kernel<<<gridA, 256>>>(x, emb, Wif, bf, Wib, bb);
    lstm_kernel<<<128, 256, smemB>>>(Whf, Whb);
    fc_kernel<<<TT, 256, smemC>>>(fc1W, fc1b, clsW, clsb);
    viterbi_kernel<<<BB / 4, 128, smemD>>>(trans, out);
}